// round 9
// baseline (speedup 1.0000x reference)
#include <cuda_runtime.h>

typedef unsigned long long u64;

#define S_ 512
#define B_ 64
#define H_ 1024
#define G_ 4096   // 4*H
#define NCTA_ 128

// ---------------- scratch (__device__ globals; allocation-free rule) --------
__device__ float g_y0[(size_t)S_ * (size_t)B_ * (size_t)H_];   // layer-0 y (layer-1 input)
__device__ float g_ht[2 * (size_t)B_ * (size_t)H_];            // layer-1 h ping-pong
__device__ float g_wr[(size_t)256 * 32768];                    // rearranged W: [which*128+cta][256 k4][128]
__device__ unsigned g_barCnt = 0;
__device__ unsigned g_barGen = 0;

// ---------------- packed fp32x2 helpers ----------------
__device__ __forceinline__ void fma2(u64 &d, u64 a, u64 b) {
    asm("fma.rn.f32x2 %0, %1, %2, %0;" : "+l"(d) : "l"(a), "l"(b));
}
__device__ __forceinline__ float2 unpack2(u64 v) {
    float2 f; asm("mov.b64 {%0, %1}, %2;" : "=f"(f.x), "=f"(f.y) : "l"(v)); return f;
}
__device__ __forceinline__ float hsum2(u64 v) {
    float2 f = unpack2(v); return f.x + f.y;
}
__device__ __forceinline__ float sigf(float x) { return 1.0f / (1.0f + __expf(-x)); }
__device__ __forceinline__ float tanhf_(float x) { return 2.0f / (1.0f + __expf(-2.0f * x)) - 1.0f; }

__device__ __forceinline__ void cpasync16(float* dst_smem, const float* src) {
    unsigned d = (unsigned)__cvta_generic_to_shared(dst_smem);
    asm volatile("cp.async.cg.shared.global [%0], [%1], 16;" :: "r"(d), "l"(src));
}
__device__ __forceinline__ void barx(int id) {
    asm volatile("bar.sync %0, 128;" :: "r"(id) : "memory");
}

// Device-wide barrier (sense-reversing, NCTA_ resident CTAs)
__device__ __forceinline__ void gsync() {
    __syncthreads();
    if (threadIdx.x == 0) {
        __threadfence();
        unsigned my = *(volatile unsigned*)&g_barGen;
        if (atomicAdd(&g_barCnt, 1) == NCTA_ - 1) {
            atomicExch(&g_barCnt, 0);
            __threadfence();
            atomicExch(&g_barGen, my + 1);
        } else {
            while (*(volatile unsigned*)&g_barGen == my) __nanosleep(32);
        }
        __threadfence();
    }
    __syncthreads();
}

// ---------------- 4x4 register-tile inner kernel (round-7, proven) ----------
struct Ops {
    ulonglong2 w0, w1, w2, w3;
    ulonglong2 h0, h1, h2, h3;
};
__device__ __forceinline__ void load_ops(Ops &o, const float* wp, const float* hp) {
    o.w0 = *(const ulonglong2*)(wp + 0);
    o.w1 = *(const ulonglong2*)(wp + 32);
    o.w2 = *(const ulonglong2*)(wp + 64);
    o.w3 = *(const ulonglong2*)(wp + 96);
    o.h0 = *(const ulonglong2*)(hp + 0 * 24);
    o.h1 = *(const ulonglong2*)(hp + 4 * 24);
    o.h2 = *(const ulonglong2*)(hp + 8 * 24);
    o.h3 = *(const ulonglong2*)(hp + 12 * 24);
}
__device__ __forceinline__ void do_fma(u64 (&acc)[4][4], const Ops &o) {
    fma2(acc[0][0], o.w0.x, o.h0.x); fma2(acc[0][0], o.w0.y, o.h0.y);
    fma2(acc[1][0], o.w1.x, o.h0.x); fma2(acc[1][0], o.w1.y, o.h0.y);
    fma2(acc[2][0], o.w2.x, o.h0.x); fma2(acc[2][0], o.w2.y, o.h0.y);
    fma2(acc[3][0], o.w3.x, o.h0.x); fma2(acc[3][0], o.w3.y, o.h0.y);
    fma2(acc[0][1], o.w0.x, o.h1.x); fma2(acc[0][1], o.w0.y, o.h1.y);
    fma2(acc[1][1], o.w1.x, o.h1.x); fma2(acc[1][1], o.w1.y, o.h1.y);
    fma2(acc[2][1], o.w2.x, o.h1.x); fma2(acc[2][1], o.w2.y, o.h1.y);
    fma2(acc[3][1], o.w3.x, o.h1.x); fma2(acc[3][1], o.w3.y, o.h1.y);
    fma2(acc[0][2], o.w0.x, o.h2.x); fma2(acc[0][2], o.w0.y, o.h2.y);
    fma2(acc[1][2], o.w1.x, o.h2.x); fma2(acc[1][2], o.w1.y, o.h2.y);
    fma2(acc[2][2], o.w2.x, o.h2.x); fma2(acc[2][2], o.w2.y, o.h2.y);
    fma2(acc[3][2], o.w3.x, o.h2.x); fma2(acc[3][2], o.w3.y, o.h2.y);
    fma2(acc[0][3], o.w0.x, o.h3.x); fma2(acc[0][3], o.w0.y, o.h3.y);
    fma2(acc[1][3], o.w1.x, o.h3.x); fma2(acc[1][3], o.w1.y, o.h3.y);
    fma2(acc[2][3], o.w2.x, o.h3.x); fma2(acc[2][3], o.w2.y, o.h3.y);
    fma2(acc[3][3], o.w3.x, o.h3.x); fma2(acc[3][3], o.w3.y, o.h3.y);
}

// ---------------- smem plan (floats) ----------------
// HB: per-warp x/h stages: 16 warps x 4 stages x (16 rows x stride 24) = 24576
// WB: per-ks shared w stages: 4 ks x 4 stages x 512                    =  8192
// CMB: [4 ks][64 b][36]                                                =  9216
// GIS: [64 b][36]  (gi for next step)                                  =  2304
#define HB_OFF   0
#define WB_OFF   24576
#define CMB_OFF  32768
#define GIS_OFF  41984
#define SMEM_F   44288
#define SMEM_FUSED (SMEM_F * 4)

// issue one 16k chunk: per-warp x rows + (bg==0) shared w block; one commit group
__device__ __forceinline__ void issue_chunk(
    int ch, const float* __restrict__ wsrc, const float* __restrict__ xsrc,
    float* hst, float* wst, int lane, int ks, int wb0, int bg)
{
    float* hd = hst + (ch & 3) * 384;
    const float* xs = xsrc + ks * 256 + ch * 16;
#pragma unroll
    for (int q = 0; q < 2; q++) {
        int li = lane + 32 * q;
        int rowb = li & 15, kq = li >> 4;
        cpasync16(hd + rowb * 24 + kq * 4, xs + (size_t)(wb0 + rowb) * H_ + kq * 4);
    }
    if (bg == 0) {
        float* wd = wst + (ch & 3) * 512;
        const float* ws = wsrc + (size_t)(ks * 64 + ch * 4) * 128;
#pragma unroll
        for (int q = 0; q < 4; q++)
            cpasync16(wd + q * 128 + lane * 4, ws + q * 128 + lane * 4);
    }
    asm volatile("cp.async.commit_group;");
}

// 16-chunk mainloop over this warp's 256-k slice (4-stage pipeline)
__device__ __forceinline__ void mainloop16(
    u64 (&acc)[4][4],
    const float* __restrict__ wsrc, const float* __restrict__ xsrc,
    float* hst, float* wst,
    int lane, int ks, int wb0, int bg, int ly, int lx)
{
    issue_chunk(0, wsrc, xsrc, hst, wst, lane, ks, wb0, bg);
    issue_chunk(1, wsrc, xsrc, hst, wst, lane, ks, wb0, bg);
    issue_chunk(2, wsrc, xsrc, hst, wst, lane, ks, wb0, bg);
#pragma unroll 2
    for (int ch = 0; ch < 16; ch++) {
        if (ch < 14)      asm volatile("cp.async.wait_group 2;" ::: "memory");
        else if (ch == 14) asm volatile("cp.async.wait_group 1;" ::: "memory");
        else               asm volatile("cp.async.wait_group 0;" ::: "memory");
        barx(1 + ks);     // w-stage for this chunk is ready (staging warp waited too)

        const float* wbase = wst + (ch & 3) * 512 + ly * 4;
        const float* hbase = hst + (ch & 3) * 384 + lx * 24;
        Ops o0, o1;
        load_ops(o0, wbase, hbase);
        load_ops(o1, wbase + 128, hbase + 4);
        do_fma(acc, o0);
        load_ops(o0, wbase + 256, hbase + 8);
        do_fma(acc, o1);
        load_ops(o1, wbase + 384, hbase + 12);
        do_fma(acc, o0);
        do_fma(acc, o1);
        __syncwarp();
        if (ch + 3 < 16)
            issue_chunk(ch + 3, wsrc, xsrc, hst, wst, lane, ks, wb0, bg);
    }
}

// ============================================================================
// Fused persistent layer: recurrence + NEXT-step input projection per step.
// 128 CTAs x 512 threads; CTA owns 8 hidden x 4 gates (32 cols) x 64 batches.
// Warp wy: ks = wy>>2 (k-slice of 256), bg = wy&3 (16 batches). Both W matrices
// streamed from pre-rearranged global scratch via shared per-ks smem stages.
// ============================================================================
__global__ __launch_bounds__(512, 1) void lstm_fused(
    int layer, const float* __restrict__ whh, const float* __restrict__ wih,
    const float* __restrict__ xin_,
    const float* __restrict__ bih, const float* __restrict__ bhh,
    float* __restrict__ y1, float* __restrict__ hn_base, float* __restrict__ cn_base)
{
    extern __shared__ float sm[];
    float* HB  = sm + HB_OFF;
    float* WB  = sm + WB_OFF;
    float* Cmb = sm + CMB_OFF;
    float* GIS = sm + GIS_OFF;

    const size_t BH = (size_t)B_ * H_;
    int tid = threadIdx.x, lane = tid & 31, wy = tid >> 5;
    int ks = wy >> 2, bg = wy & 3;
    int wb0 = bg * 16;
    int lx = lane & 3, ly = lane >> 2;
    int jb = blockIdx.x * 8;

    const float* xin = (layer == 0) ? xin_ : (const float*)g_y0;

    // ---- prologue: rearrange W_hh and W_ih slices to chunked global scratch
    float* wr0 = g_wr + (size_t)blockIdx.x * 32768;
    float* wr1 = g_wr + (size_t)(128 + blockIdx.x) * 32768;
    {
        int c = tid & 31;
        int wn = ((c >> 3) * H_) + jb + (c & 7);
        int dstbase = (c & 3) * 32 + (c >> 2) * 4;
        int k4b = tid >> 5;
        const float* wh = whh + (size_t)wn * H_;
        const float* wi = wih + (size_t)wn * H_;
#pragma unroll
        for (int q = 0; q < 16; q++) {
            int k4 = k4b + q * 16;
            *(float4*)&wr0[(size_t)k4 * 128 + dstbase] = *(const float4*)(wh + k4 * 4);
            *(float4*)&wr1[(size_t)k4 * 128 + dstbase] = *(const float4*)(wi + k4 * 4);
        }
    }
    __threadfence();
    __syncthreads();

    float* hst = HB + wy * 1536;     // 4 stages x 384
    float* wst = WB + ks * 2048;     // 4 stages x 512 (shared by ks group)

    // cell mapping (one cell per thread) + per-thread bias sums
    int cb = tid >> 3, cj = tid & 7;
    float cst = 0.0f;
    float bsum[4];
#pragma unroll
    for (int g = 0; g < 4; g++) {
        int n = g * H_ + jb + cj;
        bsum[g] = bih[n] + bhh[n];
    }

    for (int t = -1; t < S_; t++) {
        if (t >= 0) {
            // gi for this step (from GIS, written last step)
            float4 gi4[4];
            if (ks == 0) {
#pragma unroll
                for (int rr = 0; rr < 4; rr++)
                    gi4[rr] = *(const float4*)&GIS[(wb0 + lx + 4 * rr) * 36 + ly * 4];
            }

            u64 acc[4][4];
#pragma unroll
            for (int cc = 0; cc < 4; cc++)
#pragma unroll
                for (int rr = 0; rr < 4; rr++) acc[cc][rr] = 0ull;

            if (t > 0) {
                const float* hsrc = (layer == 0)
                    ? (g_y0 + (size_t)(t - 1) * BH)
                    : (g_ht + (size_t)((t - 1) & 1) * BH);
                mainloop16(acc, wr0, hsrc, hst, wst, lane, ks, wb0, bg, ly, lx);
            }

            // publish recurrence partials (+ gi on ks==0)
#pragma unroll
            for (int rr = 0; rr < 4; rr++) {
                float4 v;
                v.x = hsum2(acc[0][rr]);
                v.y = hsum2(acc[1][rr]);
                v.z = hsum2(acc[2][rr]);
                v.w = hsum2(acc[3][rr]);
                if (ks == 0) {
                    v.x += gi4[rr].x; v.y += gi4[rr].y;
                    v.z += gi4[rr].z; v.w += gi4[rr].w;
                }
                int b = wb0 + lx + 4 * rr;
                *(float4*)&Cmb[(ks * 64 + b) * 36 + ly * 4] = v;
            }
            __syncthreads();

            // cell update
            float z[4];
#pragma unroll
            for (int g = 0; g < 4; g++) {
                int idx = g * 8 + cj;
                z[g] = Cmb[(0 * 64 + cb) * 36 + idx]
                     + Cmb[(1 * 64 + cb) * 36 + idx]
                     + Cmb[(2 * 64 + cb) * 36 + idx]
                     + Cmb[(3 * 64 + cb) * 36 + idx];
            }
            cst = sigf(z[1]) * cst + sigf(z[0]) * tanhf_(z[2]);
            float hv = sigf(z[3]) * tanhf_(cst);

            float* hdst = (layer == 0) ? (g_y0 + (size_t)t * BH)
                                       : (g_ht + (size_t)(t & 1) * BH);
            size_t hoff = (size_t)cb * H_ + jb + cj;
            hdst[hoff] = hv;
            if (layer == 1)
                y1[(size_t)t * BH + hoff] = hv;
            if (t == S_ - 1) {
                size_t o = (size_t)layer * BH + hoff;
                hn_base[o] = hv;
                cn_base[o] = cst;
            }
            __syncthreads();   // Cmb consumed; safe for gi publish below
        }

        if (t + 1 < S_) {
            // input projection for step t+1 (CTA-local slice)
            u64 acc[4][4];
#pragma unroll
            for (int cc = 0; cc < 4; cc++)
#pragma unroll
                for (int rr = 0; rr < 4; rr++) acc[cc][rr] = 0ull;

            mainloop16(acc, wr1, xin + (size_t)(t + 1) * BH, hst, wst,
                       lane, ks, wb0, bg, ly, lx);

#pragma unroll
            for (int rr = 0; rr < 4; rr++) {
                float4 v;
                v.x = hsum2(acc[0][rr]);
                v.y = hsum2(acc[1][rr]);
                v.z = hsum2(acc[2][rr]);
                v.w = hsum2(acc[3][rr]);
                int b = wb0 + lx + 4 * rr;
                *(float4*)&Cmb[(ks * 64 + b) * 36 + ly * 4] = v;
            }
            __syncthreads();

            // reduce k-slices + biases into GIS for next step
#pragma unroll
            for (int g = 0; g < 4; g++) {
                int idx = g * 8 + cj;
                GIS[cb * 36 + idx] =
                      Cmb[(0 * 64 + cb) * 36 + idx]
                    + Cmb[(1 * 64 + cb) * 36 + idx]
                    + Cmb[(2 * 64 + cb) * 36 + idx]
                    + Cmb[(3 * 64 + cb) * 36 + idx]
                    + bsum[g];
            }
        }
        gsync();
    }
}

// ============================================================================
// kernel_launch: 2 graph nodes.
// Output layout: y1 [S,B,H] | h_n [2,B,H] | c_n [2,B,H]
// ============================================================================
extern "C" void kernel_launch(void* const* d_in, const int* in_sizes, int n_in,
                              void* d_out, int out_size)
{
    const float* x     = (const float*)d_in[0];
    const float* w_ih0 = (const float*)d_in[1];
    const float* w_hh0 = (const float*)d_in[2];
    const float* b_ih0 = (const float*)d_in[3];
    const float* b_hh0 = (const float*)d_in[4];
    const float* w_ih1 = (const float*)d_in[5];
    const float* w_hh1 = (const float*)d_in[6];
    const float* b_ih1 = (const float*)d_in[7];
    const float* b_hh1 = (const float*)d_in[8];

    float* y1 = (float*)d_out;
    float* hn = y1 + (size_t)S_ * B_ * H_;
    float* cn = hn + 2 * (size_t)B_ * H_;

    cudaFuncSetAttribute(lstm_fused, cudaFuncAttributeMaxDynamicSharedMemorySize, SMEM_FUSED);

    lstm_fused<<<NCTA_, 512, SMEM_FUSED>>>(0, w_hh0, w_ih0, x, b_ih0, b_hh0, y1, hn, cn);
    lstm_fused<<<NCTA_, 512, SMEM_FUSED>>>(1, w_hh1, w_ih1, x, b_ih1, b_hh1, y1, hn, cn);
}

// round 10
// speedup vs baseline: 1.2489x; 1.2489x over previous
#include <cuda_runtime.h>

typedef unsigned long long u64;

#define S_ 512
#define B_ 64
#define H_ 1024
#define G_ 4096   // 4*H
#define NCTA_ 128

// ---------------- scratch (__device__ globals; allocation-free rule) --------
__device__ float g_gi[(size_t)S_ * (size_t)B_ * (size_t)G_];   // 512 MB
__device__ float g_y0[(size_t)S_ * (size_t)B_ * (size_t)H_];   // layer-0 h history [t][b][h]
__device__ int   g_flag[NCTA_];                                // per-CTA step progress
__device__ unsigned g_barCnt = 0;
__device__ unsigned g_barGen = 0;

// ---------------- packed fp32x2 helpers ----------------
__device__ __forceinline__ u64 pack_dup(float x) {
    u64 r; asm("mov.b64 %0, {%1, %1};" : "=l"(r) : "f"(x)); return r;
}
__device__ __forceinline__ void fma2(u64 &d, u64 a, u64 b) {
    asm("fma.rn.f32x2 %0, %1, %2, %0;" : "+l"(d) : "l"(a), "l"(b));
}
__device__ __forceinline__ float2 unpack2(u64 v) {
    float2 f; asm("mov.b64 {%0, %1}, %2;" : "=f"(f.x), "=f"(f.y) : "l"(v)); return f;
}
__device__ __forceinline__ float hsum2(u64 v) {
    float2 f = unpack2(v); return f.x + f.y;
}
__device__ __forceinline__ float sigf(float x) { return 1.0f / (1.0f + __expf(-x)); }
__device__ __forceinline__ float tanhf_(float x) { return 2.0f / (1.0f + __expf(-2.0f * x)) - 1.0f; }

__device__ __forceinline__ void cpasync16(float* dst_smem, const float* src) {
    unsigned d = (unsigned)__cvta_generic_to_shared(dst_smem);
    asm volatile("cp.async.cg.shared.global [%0], [%1], 16;" :: "r"(d), "l"(src));
}

// Device-wide barrier — used ONCE per launch (orders the flag reset).
__device__ __forceinline__ void gsync() {
    __syncthreads();
    if (threadIdx.x == 0) {
        __threadfence();
        unsigned my = *(volatile unsigned*)&g_barGen;
        if (atomicAdd(&g_barCnt, 1) == NCTA_ - 1) {
            atomicExch(&g_barCnt, 0);
            __threadfence();
            atomicExch(&g_barGen, my + 1);
        } else {
            while (*(volatile unsigned*)&g_barGen == my) __nanosleep(32);
        }
        __threadfence();
    }
    __syncthreads();
}

// ============================================================================
// Input projection GEMM (round-7, proven 60%): GI[m,n] = A[m,:]·W[n,:] + biases
// ============================================================================
__global__ __launch_bounds__(256, 2) void gemm_gi(
    int layer, const float* __restrict__ Xin,
    const float* __restrict__ W,
    const float* __restrict__ bih, const float* __restrict__ bhh)
{
    __shared__ __align__(16) float As[2][16][128];
    __shared__ __align__(16) float Bs[2][16][128];
    const float* A = layer ? g_y0 : Xin;
    float* GI = g_gi;
    const int K = H_;
    int bn = blockIdx.x, bm = blockIdx.y;
    int t = threadIdx.x;
    int tx = t & 15, ty = t >> 4;
    int lr = t >> 1;
    int lc = (t & 1) * 8;

    const float* Ap = A + (size_t)(bm * 128 + lr) * K + lc;
    const float* Bp = W + (size_t)(bn * 128 + lr) * K + lc;

    u64 acc[8][4];
#pragma unroll
    for (int i = 0; i < 8; i++)
#pragma unroll
        for (int j = 0; j < 4; j++) acc[i][j] = 0ull;

    float4 ra0, ra1, rb0, rb1;
    ra0 = *(const float4*)(Ap + 0);
    ra1 = *(const float4*)(Ap + 4);
    rb0 = *(const float4*)(Bp + 0);
    rb1 = *(const float4*)(Bp + 4);

    As[0][lc + 0][lr] = ra0.x; As[0][lc + 1][lr] = ra0.y; As[0][lc + 2][lr] = ra0.z; As[0][lc + 3][lr] = ra0.w;
    As[0][lc + 4][lr] = ra1.x; As[0][lc + 5][lr] = ra1.y; As[0][lc + 6][lr] = ra1.z; As[0][lc + 7][lr] = ra1.w;
    Bs[0][lc + 0][lr] = rb0.x; Bs[0][lc + 1][lr] = rb0.y; Bs[0][lc + 2][lr] = rb0.z; Bs[0][lc + 3][lr] = rb0.w;
    Bs[0][lc + 4][lr] = rb1.x; Bs[0][lc + 5][lr] = rb1.y; Bs[0][lc + 6][lr] = rb1.z; Bs[0][lc + 7][lr] = rb1.w;
    __syncthreads();

    for (int kt = 0; kt < K / 16; kt++) {
        int cur = kt & 1;
        if (kt + 1 < K / 16) {
            int k0 = (kt + 1) * 16;
            ra0 = *(const float4*)(Ap + k0);
            ra1 = *(const float4*)(Ap + k0 + 4);
            rb0 = *(const float4*)(Bp + k0);
            rb1 = *(const float4*)(Bp + k0 + 4);
        }
#pragma unroll
        for (int k = 0; k < 16; k++) {
            float4 av0 = *(const float4*)&As[cur][k][ty * 8];
            float4 av1 = *(const float4*)&As[cur][k][ty * 8 + 4];
            const ulonglong2* bp2 = (const ulonglong2*)&Bs[cur][k][tx * 8];
            ulonglong2 bA = bp2[0], bB = bp2[1];
            float a_[8] = {av0.x, av0.y, av0.z, av0.w, av1.x, av1.y, av1.z, av1.w};
#pragma unroll
            for (int i = 0; i < 8; i++) {
                u64 ad = pack_dup(a_[i]);
                fma2(acc[i][0], ad, bA.x);
                fma2(acc[i][1], ad, bA.y);
                fma2(acc[i][2], ad, bB.x);
                fma2(acc[i][3], ad, bB.y);
            }
        }
        if (kt + 1 < K / 16) {
            int nxt = cur ^ 1;
            As[nxt][lc + 0][lr] = ra0.x; As[nxt][lc + 1][lr] = ra0.y; As[nxt][lc + 2][lr] = ra0.z; As[nxt][lc + 3][lr] = ra0.w;
            As[nxt][lc + 4][lr] = ra1.x; As[nxt][lc + 5][lr] = ra1.y; As[nxt][lc + 6][lr] = ra1.z; As[nxt][lc + 7][lr] = ra1.w;
            Bs[nxt][lc + 0][lr] = rb0.x; Bs[nxt][lc + 1][lr] = rb0.y; Bs[nxt][lc + 2][lr] = rb0.z; Bs[nxt][lc + 3][lr] = rb0.w;
            Bs[nxt][lc + 4][lr] = rb1.x; Bs[nxt][lc + 5][lr] = rb1.y; Bs[nxt][lc + 6][lr] = rb1.z; Bs[nxt][lc + 7][lr] = rb1.w;
            __syncthreads();
        }
    }

    int row0 = bm * 128 + ty * 8, col0 = bn * 128 + tx * 8;
#pragma unroll
    for (int i = 0; i < 8; i++) {
#pragma unroll
        for (int jp = 0; jp < 4; jp++) {
            float2 v = unpack2(acc[i][jp]);
            int n0 = col0 + jp * 2;
            GI[(size_t)(row0 + i) * G_ + n0]     = v.x + bih[n0]     + bhh[n0];
            GI[(size_t)(row0 + i) * G_ + n0 + 1] = v.y + bih[n0 + 1] + bhh[n0 + 1];
        }
    }
}

// ============================================================================
// Persistent recurrent layer, round-7 structure, NO per-step global barrier.
// Cross-CTA sync via per-CTA progress flags: warp ks waits only for its 32
// producer CTAs [32ks, 32ks+32) to have finished step t-1. h history is kept
// per-step (g_y0 for layer 0, y1/d_out for layer 1) so CTA skew is hazard-free.
// ============================================================================
#define WSM_F   (256 * 32 * 4)
#define HSTG_F  (16 * 24)
#define HBUF_F  (16 * 2 * HSTG_F)
#define CMB_F   (4 * 64 * 36)
#define SMEM_STEP ((WSM_F + HBUF_F + CMB_F) * 4)

struct Ops {
    ulonglong2 w0, w1, w2, w3;
    ulonglong2 h0, h1, h2, h3;
};
__device__ __forceinline__ void load_ops(Ops &o, const float* wp, const float* hp) {
    o.w0 = *(const ulonglong2*)(wp + 0);
    o.w1 = *(const ulonglong2*)(wp + 32);
    o.w2 = *(const ulonglong2*)(wp + 64);
    o.w3 = *(const ulonglong2*)(wp + 96);
    o.h0 = *(const ulonglong2*)(hp + 0 * 24);
    o.h1 = *(const ulonglong2*)(hp + 4 * 24);
    o.h2 = *(const ulonglong2*)(hp + 8 * 24);
    o.h3 = *(const ulonglong2*)(hp + 12 * 24);
}
__device__ __forceinline__ void do_fma(u64 (&acc)[4][4], const Ops &o) {
    fma2(acc[0][0], o.w0.x, o.h0.x); fma2(acc[0][0], o.w0.y, o.h0.y);
    fma2(acc[1][0], o.w1.x, o.h0.x); fma2(acc[1][0], o.w1.y, o.h0.y);
    fma2(acc[2][0], o.w2.x, o.h0.x); fma2(acc[2][0], o.w2.y, o.h0.y);
    fma2(acc[3][0], o.w3.x, o.h0.x); fma2(acc[3][0], o.w3.y, o.h0.y);
    fma2(acc[0][1], o.w0.x, o.h1.x); fma2(acc[0][1], o.w0.y, o.h1.y);
    fma2(acc[1][1], o.w1.x, o.h1.x); fma2(acc[1][1], o.w1.y, o.h1.y);
    fma2(acc[2][1], o.w2.x, o.h1.x); fma2(acc[2][1], o.w2.y, o.h1.y);
    fma2(acc[3][1], o.w3.x, o.h1.x); fma2(acc[3][1], o.w3.y, o.h1.y);
    fma2(acc[0][2], o.w0.x, o.h2.x); fma2(acc[0][2], o.w0.y, o.h2.y);
    fma2(acc[1][2], o.w1.x, o.h2.x); fma2(acc[1][2], o.w1.y, o.h2.y);
    fma2(acc[2][2], o.w2.x, o.h2.x); fma2(acc[2][2], o.w2.y, o.h2.y);
    fma2(acc[3][2], o.w3.x, o.h2.x); fma2(acc[3][2], o.w3.y, o.h2.y);
    fma2(acc[0][3], o.w0.x, o.h3.x); fma2(acc[0][3], o.w0.y, o.h3.y);
    fma2(acc[1][3], o.w1.x, o.h3.x); fma2(acc[1][3], o.w1.y, o.h3.y);
    fma2(acc[2][3], o.w2.x, o.h3.x); fma2(acc[2][3], o.w2.y, o.h3.y);
    fma2(acc[3][3], o.w3.x, o.h3.x); fma2(acc[3][3], o.w3.y, o.h3.y);
}

__global__ __launch_bounds__(512, 1) void lstm_layer(
    int layer, const float* __restrict__ whh,
    float* __restrict__ y1, float* __restrict__ hn_base, float* __restrict__ cn_base)
{
    extern __shared__ float sm[];
    float* Wsm  = sm;
    float* Hbuf = sm + WSM_F;
    float* Cmb  = sm + WSM_F + HBUF_F;

    const size_t BH = (size_t)B_ * H_;
    int tid  = threadIdx.x;
    int lane = tid & 31;
    int wy   = tid >> 5;
    int ks   = wy & 3;
    int wb0  = (wy >> 2) * 16;
    int lx   = lane & 3;
    int ly   = lane >> 2;
    int jb   = blockIdx.x * 8;

    // h history bases (full per-step history for both layers -> skew-safe)
    float* hbase_ = (layer == 0) ? g_y0 : y1;

    // ---- load W_hh slice into conflict-free chunked smem ----
    {
        int c = tid & 31;
        int wn = ((c >> 3) * H_) + jb + (c & 7);
        const float* wrow = whh + (size_t)wn * H_;
        int dstbase = (c & 3) * 32 + (c >> 2) * 4;
        int k4b = tid >> 5;
#pragma unroll
        for (int q = 0; q < 16; q++) {
            int k4 = k4b + q * 16;
            float4 v = *(const float4*)(wrow + k4 * 4);
            *(float4*)&Wsm[k4 * 128 + dstbase] = v;
        }
    }
    // reset own flag; one global barrier orders resets vs. polls
    if (tid == 0) ((volatile int*)g_flag)[blockIdx.x] = 0;
    gsync();

    float* hwbuf = Hbuf + wy * (2 * HSTG_F);
    int n_base = ((ly >> 1) * H_) + jb + ((ly & 1) * 4);
    int cb = tid >> 3, cj = tid & 7;
    float cst = 0.0f;
    int myprod = ks * 32 + lane;   // this lane's producer CTA for warp's k-slice

    for (int t = 0; t < S_; t++) {
        const float* gi_t = g_gi + (size_t)t * B_ * G_;
        float4 gi4[4];
        if (ks == 0) {
#pragma unroll
            for (int rr = 0; rr < 4; rr++)
                gi4[rr] = *(const float4*)(gi_t + (size_t)(wb0 + lx + 4 * rr) * G_ + n_base);
        }

        u64 acc[4][4];
#pragma unroll
        for (int cc = 0; cc < 4; cc++)
#pragma unroll
            for (int rr = 0; rr < 4; rr++) acc[cc][rr] = 0ull;

        if (t > 0) {
            // wait for the 32 producer CTAs of this warp's k-slice
            for (;;) {
                int v = ((volatile int*)g_flag)[myprod];
                if (__all_sync(0xffffffffu, v >= t)) break;
                __nanosleep(64);
            }
            __threadfence();   // acquire: order h reads after flag observation

            const float* hsrc = hbase_ + (size_t)(t - 1) * BH;
            const float* hk = hsrc + ks * 256;

#pragma unroll
            for (int q = 0; q < 2; q++) {
                int li = lane + 32 * q;
                int rowb = li & 15, kq = li >> 4;
                cpasync16(hwbuf + rowb * 24 + kq * 4,
                          hk + (size_t)(wb0 + rowb) * H_ + kq * 4);
            }
            asm volatile("cp.async.commit_group;");

            for (int ch = 0; ch < 16; ch++) {
                if (ch < 15) {
                    float* dst = hwbuf + ((ch + 1) & 1) * HSTG_F;
                    const float* src = hk + (ch + 1) * 16;
#pragma unroll
                    for (int q = 0; q < 2; q++) {
                        int li = lane + 32 * q;
                        int rowb = li & 15, kq = li >> 4;
                        cpasync16(dst + rowb * 24 + kq * 4,
                                  src + (size_t)(wb0 + rowb) * H_ + kq * 4);
                    }
                    asm volatile("cp.async.commit_group;");
                    asm volatile("cp.async.wait_group 1;");
                } else {
                    asm volatile("cp.async.wait_group 0;");
                }
                __syncwarp();

                const float* hs = hwbuf + (ch & 1) * HSTG_F;
                int k4g0 = ks * 64 + ch * 4;
                const float* wbase = Wsm + (size_t)k4g0 * 128 + ly * 4;
                const float* hb = hs + lx * 24;

                Ops ops0, ops1;
                load_ops(ops0, wbase, hb);
                load_ops(ops1, wbase + 128, hb + 4);
                do_fma(acc, ops0);
                load_ops(ops0, wbase + 256, hb + 8);
                do_fma(acc, ops1);
                load_ops(ops1, wbase + 384, hb + 12);
                do_fma(acc, ops0);
                do_fma(acc, ops1);

                __syncwarp();
            }
        }

        // publish partials (k-slice 0 folds gi in)
#pragma unroll
        for (int rr = 0; rr < 4; rr++) {
            float4 v;
            v.x = hsum2(acc[0][rr]);
            v.y = hsum2(acc[1][rr]);
            v.z = hsum2(acc[2][rr]);
            v.w = hsum2(acc[3][rr]);
            if (ks == 0) {
                v.x += gi4[rr].x; v.y += gi4[rr].y;
                v.z += gi4[rr].z; v.w += gi4[rr].w;
            }
            int b = wb0 + lx + 4 * rr;
            *(float4*)&Cmb[(ks * 64 + b) * 36 + ly * 4] = v;
        }
        __syncthreads();

        // combine k-slices + cell update: one cell per thread
        float z[4];
#pragma unroll
        for (int g = 0; g < 4; g++) {
            int c = g * 8 + cj;
            z[g] = Cmb[(0 * 64 + cb) * 36 + c]
                 + Cmb[(1 * 64 + cb) * 36 + c]
                 + Cmb[(2 * 64 + cb) * 36 + c]
                 + Cmb[(3 * 64 + cb) * 36 + c];
        }
        cst = sigf(z[1]) * cst + sigf(z[0]) * tanhf_(z[2]);
        float hv = sigf(z[3]) * tanhf_(cst);

        size_t hoff = (size_t)cb * H_ + jb + cj;
        (hbase_ + (size_t)t * BH)[hoff] = hv;
        if (t == S_ - 1) {
            size_t o = (size_t)layer * BH + hoff;
            hn_base[o] = hv;
            cn_base[o] = cst;
        }

        // all h stores of this CTA done -> publish progress flag (release)
        __syncthreads();
        if (tid == 0) {
            __threadfence();
            atomicExch(&g_flag[blockIdx.x], t + 1);
        }
        // NOTE: no further CTA-wide wait needed; Cmb is not written until the
        // next publish phase, which is preceded by the mainloop (long) or, at
        // worst, by the gi loads — but the next write to Cmb by any thread
        // happens after this __syncthreads() in its own iteration path.
        __syncthreads();
    }
}

// ============================================================================
// kernel_launch: 4 graph nodes.
// Output layout: y1 [S,B,H] | h_n [2,B,H] | c_n [2,B,H]
// ============================================================================
extern "C" void kernel_launch(void* const* d_in, const int* in_sizes, int n_in,
                              void* d_out, int out_size)
{
    const float* x     = (const float*)d_in[0];
    const float* w_ih0 = (const float*)d_in[1];
    const float* w_hh0 = (const float*)d_in[2];
    const float* b_ih0 = (const float*)d_in[3];
    const float* b_hh0 = (const float*)d_in[4];
    const float* w_ih1 = (const float*)d_in[5];
    const float* w_hh1 = (const float*)d_in[6];
    const float* b_ih1 = (const float*)d_in[7];
    const float* b_hh1 = (const float*)d_in[8];

    float* y1 = (float*)d_out;
    float* hn = y1 + (size_t)S_ * B_ * H_;
    float* cn = hn + 2 * (size_t)B_ * H_;

    cudaFuncSetAttribute(lstm_layer, cudaFuncAttributeMaxDynamicSharedMemorySize, SMEM_STEP);

    dim3 ggrid(G_ / 128, (S_ * B_) / 128);  // (32, 256)

    gemm_gi<<<ggrid, 256>>>(0, x, w_ih0, b_ih0, b_hh0);
    lstm_layer<<<NCTA_, 512, SMEM_STEP>>>(0, w_hh0, y1, hn, cn);
    gemm_gi<<<ggrid, 256>>>(1, x, w_ih1, b_ih1, b_hh1);
    lstm_layer<<<NCTA_, 512, SMEM_STEP>>>(1, w_hh1, y1, hn, cn);
}